// round 3
// baseline (speedup 1.0000x reference)
#include <cuda_runtime.h>
#include <cuda_fp16.h>

// Problem constants
#define Bn   64
#define Rn   4608
#define Cn   32
#define INn  8
#define OUTn 16
#define RCHUNK 64
#define NCHUNK 72    // Rn / RCHUNK
#define RPASS  128
#define NSPLIT 36    // Rn / RPASS

// Scratch (device globals; allocation-free per harness rules)
// u_hat layout: [c][r][h(2)][b(64)] of uint4 (8 fp16 each) -> dense 512B warp accesses
static __device__ uint4  g_uhat4[(size_t)Cn * Rn * 2 * Bn];          // 302 MB
static __device__ float4 g_xT4[(size_t)Rn * 2 * Bn];                 // x transposed: [r][h][b] float4
static __device__ float  g_part[(size_t)Cn * NCHUNK * Bn * OUTn];    // iter-1 partial sums
static __device__ float  g_red[(size_t)Cn * NSPLIT * Bn * 17];       // pass partials (n[16], d)
static __device__ float  g_v1[(size_t)Bn * Cn * OUTn];
static __device__ float  g_vcur[(size_t)Bn * Cn * OUTn];             // current logit vector

typedef unsigned long long ull;

// ---- packed f32x2 helpers ----
__device__ __forceinline__ ull pk2(float lo, float hi) {
    ull r;
    asm("mov.b64 %0, {%1, %2};" : "=l"(r) : "f"(lo), "f"(hi));
    return r;
}
__device__ __forceinline__ ull ffma2(ull a, ull b, ull c) {
    ull d;
    asm("fma.rn.f32x2 %0, %1, %2, %3;" : "=l"(d) : "l"(a), "l"(b), "l"(c));
    return d;
}
__device__ __forceinline__ float2 upk2(ull v) {
    float lo, hi;
    asm("mov.b64 {%0, %1}, %2;" : "=f"(lo), "=f"(hi) : "l"(v));
    return make_float2(lo, hi);
}

// ============================================================================
// k0: transpose x (64 b, 9216 float4) -> xT (9216 float4-rows, 64 b).
// ============================================================================
__global__ void __launch_bounds__(256)
k0_transpose(const float4* __restrict__ x4) {
    __shared__ float4 tile[32][33];
    const int f0 = blockIdx.x * 32;
    const int b0 = blockIdx.y * 32;
    const int tx = threadIdx.x;
    const int ty0 = threadIdx.y;
    #pragma unroll
    for (int j = 0; j < 4; j++) {
        int ty = ty0 * 4 + j;
        tile[ty][tx] = x4[(size_t)(b0 + ty) * (Rn * 2) + f0 + tx];
    }
    __syncthreads();
    #pragma unroll
    for (int j = 0; j < 4; j++) {
        int ty = ty0 * 4 + j;
        g_xT4[(size_t)(f0 + ty) * Bn + b0 + tx] = tile[tx][ty];
    }
}

// ============================================================================
// k1: u_hat (fp16) + exact fp32 partial sums for the iteration-1 mean.
// Grid (Cn, NCHUNK), block 256 = 16 rgroups x 16 b-quads.
// Each thread: 4 batches x 4 routes. W smem-staged; LDS amortized 4x over b.
// ============================================================================
__global__ void __launch_bounds__(256)
k1_uhat(const float* __restrict__ w) {
    const int c     = blockIdx.x;
    const int chunk = blockIdx.y;
    const int r0    = chunk * RCHUNK;
    const int tid   = threadIdx.x;

    __shared__ float sW[RCHUNK * 128];   // 32 KB: W[r0..r0+63][c][i][o]

    {
        const float4* wg = reinterpret_cast<const float4*>(w);
        float4*       ws = reinterpret_cast<float4*>(sW);
        #pragma unroll
        for (int t = tid; t < RCHUNK * 32; t += 256) {
            int rr = t >> 5;
            int q  = t & 31;
            ws[rr * 32 + q] = wg[((size_t)(r0 + rr) * Cn + c) * 32 + q];
        }
    }
    __syncthreads();

    const int rg = tid >> 4;          // 0..15, covers 4 r each
    const int bq = tid & 15;          // b base = bq*4

    // mean accumulators: 4 b x 8 o-pairs (f32x2)
    ull sacc[4][8];
    #pragma unroll
    for (int j = 0; j < 4; j++)
        #pragma unroll
        for (int jp = 0; jp < 8; jp++) sacc[j][jp] = 0ull;

    #pragma unroll
    for (int kk = 0; kk < 4; kk++) {
        const int rr = rg * 4 + kk;
        const int r  = r0 + rr;

        // x for 4 batches (8 floats each)
        float xv[4][8];
        #pragma unroll
        for (int j = 0; j < 4; j++) {
            float4 xa = g_xT4[((size_t)r * 2 + 0) * Bn + bq * 4 + j];
            float4 xb = g_xT4[((size_t)r * 2 + 1) * Bn + bq * 4 + j];
            xv[j][0] = xa.x; xv[j][1] = xa.y; xv[j][2] = xa.z; xv[j][3] = xa.w;
            xv[j][4] = xb.x; xv[j][5] = xb.y; xv[j][6] = xb.z; xv[j][7] = xb.w;
        }

        ull acc[4][8];
        #pragma unroll
        for (int j = 0; j < 4; j++)
            #pragma unroll
            for (int jp = 0; jp < 8; jp++) acc[j][jp] = 0ull;

        const ull* wr = reinterpret_cast<const ull*>(sW + rr * 128);
        #pragma unroll
        for (int i = 0; i < 8; i++) {
            ull wv[8];
            #pragma unroll
            for (int jp = 0; jp < 8; jp++) wv[jp] = wr[i * 8 + jp];  // broadcast LDS.64
            #pragma unroll
            for (int j = 0; j < 4; j++) {
                ull x2 = pk2(xv[j][i], xv[j][i]);
                #pragma unroll
                for (int jp = 0; jp < 8; jp++)
                    acc[j][jp] = ffma2(x2, wv[jp], acc[j][jp]);
            }
        }

        // accumulate means (packed f32x2 add), convert, store
        #pragma unroll
        for (int j = 0; j < 4; j++) {
            union { __half2 h[8]; uint4 q[2]; } cv;
            #pragma unroll
            for (int jp = 0; jp < 8; jp++) {
                asm("add.rn.f32x2 %0, %1, %2;" : "=l"(sacc[j][jp]) : "l"(sacc[j][jp]), "l"(acc[j][jp]));
                float2 u = upk2(acc[j][jp]);
                cv.h[jp] = __floats2half2_rn(u.x, u.y);
            }
            size_t base = ((size_t)(c * Rn + r) * 2) * Bn + bq * 4 + j;
            g_uhat4[base]      = cv.q[0];
            g_uhat4[base + Bn] = cv.q[1];
        }
    }

    // ---- reduce mean partials over 16 rgroups ----
    // warp = 2 rg x 16 bq; shfl_xor 16 combines rg pairs -> 8 rgroup-pairs
    float sacc_f[4][16];
    #pragma unroll
    for (int j = 0; j < 4; j++)
        #pragma unroll
        for (int jp = 0; jp < 8; jp++) {
            float2 u = upk2(sacc[j][jp]);
            sacc_f[j][2 * jp]     = u.x;
            sacc_f[j][2 * jp + 1] = u.y;
        }
    #pragma unroll
    for (int j = 0; j < 4; j++)
        #pragma unroll
        for (int o = 0; o < OUTn; o++)
            sacc_f[j][o] += __shfl_xor_sync(0xffffffffu, sacc_f[j][o], 16);

    __syncthreads();                       // done with sW contents
    float* sred = sW;                      // [8 rgp][64 b][16 o] = 32 KB
    if ((rg & 1) == 0) {
        const int rgp = rg >> 1;
        #pragma unroll
        for (int j = 0; j < 4; j++)
            #pragma unroll
            for (int o = 0; o < OUTn; o++)
                sred[((size_t)rgp * Bn + bq * 4 + j) * OUTn + o] = sacc_f[j][o];
    }
    __syncthreads();
    {
        // 256 threads x 4 (b,o) slots = 1024
        #pragma unroll
        for (int s = 0; s < 4; s++) {
            int idx = tid * 4 + s;
            int b_ = idx >> 4, o_ = idx & 15;
            float acc = 0.f;
            #pragma unroll
            for (int rgp = 0; rgp < 8; rgp++)
                acc += sred[((size_t)rgp * Bn + b_) * OUTn + o_];
            g_part[(((size_t)c * NCHUNK + chunk) * Bn + b_) * OUTn + o_] = acc;
        }
    }
}

// ============================================================================
// kf_v1: v1 = squash(mean_r u_r) per (b,c); seeds g_vcur = v1.
// ============================================================================
__global__ void __launch_bounds__(32)
kf_v1() {
    const int bc = blockIdx.x;
    const int b  = bc >> 5;
    const int c  = bc & 31;
    const int t  = threadIdx.x;

    float acc = 0.f;
    if (t < OUTn) {
        for (int ch = 0; ch < NCHUNK; ch++)
            acc += g_part[(((size_t)c * NCHUNK + ch) * Bn + b) * OUTn + t];
    }
    float val = (t < OUTn) ? acc * (1.0f / Rn) : 0.f;
    float sq = val * val;
    #pragma unroll
    for (int off = 16; off; off >>= 1) sq += __shfl_xor_sync(0xffffffffu, sq, off);
    float coef = (sq / (1.f + sq)) * rsqrtf(sq + 1e-8f);
    float v = val * coef;
    if (t < OUTn) {
        g_v1[(size_t)bc * OUTn + t]   = v;
        g_vcur[(size_t)bc * OUTn + t] = v;
    }
}

// ============================================================================
// k2p: one streaming routing pass, o-split across lane pairs.
// CTA = (c, 128-r slab). Warp = (rgroup 0..1, bquad 0..3); lane = 16 b x 2 h.
// Each thread: 64 r iters, 1 dense LDG.128 per r, 8-dim half-dot,
// shfl_xor(16) completes the 16-dim dot. ~45 regs -> high occupancy.
// ============================================================================
__global__ void __launch_bounds__(256)
k2p() {
    const int c     = blockIdx.x;
    const int split = blockIdx.y;
    const int tid   = threadIdx.x;
    const int warp  = tid >> 5;
    const int lane  = tid & 31;
    const int rg    = warp >> 2;            // 0..1 (64 r each)
    const int bq    = warp & 3;             // 0..3
    const int hh    = lane >> 4;            // 0/1 (which 8 outputs)
    const int b     = bq * 16 + (lane & 15);

    __shared__ float sV[Bn * OUTn];
    __shared__ float sRed[2][Bn][18];

    for (int t = tid; t < Bn * OUTn; t += 256) {
        int b_ = t >> 4, o_ = t & 15;
        sV[t] = g_vcur[((size_t)b_ * Cn + c) * OUTn + o_];
    }
    __syncthreads();

    float v[8];
    #pragma unroll
    for (int j = 0; j < 8; j++) v[j] = sV[b * OUTn + hh * 8 + j];

    float d = 0.f;
    float n[8];
    #pragma unroll
    for (int j = 0; j < 8; j++) n[j] = 0.f;

    const int rbase = split * RPASS + rg * 64;
    size_t base = ((size_t)(c * Rn + rbase) * 2 + hh) * Bn + b;

    #pragma unroll 4
    for (int k = 0; k < 64; k++) {
        uint4 q = g_uhat4[base + (size_t)k * 2 * Bn];
        union { __half2 h[4]; uint4 q4; } cv;
        cv.q4 = q;
        float u[8];
        #pragma unroll
        for (int j = 0; j < 4; j++) {
            float2 f = __half22float2(cv.h[j]);
            u[2 * j]     = f.x;
            u[2 * j + 1] = f.y;
        }
        float t = 0.f;
        #pragma unroll
        for (int j = 0; j < 8; j++) t = fmaf(u[j], v[j], t);
        t += __shfl_xor_sync(0xffffffffu, t, 16);       // full 16-dim dot
        float e = __expf(t);
        d += e;
        #pragma unroll
        for (int j = 0; j < 8; j++) n[j] = fmaf(e, u[j], n[j]);
    }

    // stage partials: n goes to [hh*8 ..], d only from hh==0
    #pragma unroll
    for (int j = 0; j < 8; j++) sRed[rg][b][hh * 8 + j] = n[j];
    if (hh == 0) sRed[rg][b][16] = d;
    __syncthreads();

    for (int t = tid; t < Bn * 17; t += 256) {
        int b_ = t / 17, o_ = t % 17;
        g_red[(((size_t)c * NSPLIT + split) * Bn + b_) * 17 + o_] =
            sRed[0][b_][o_] + sRed[1][b_][o_];
    }
}

// ============================================================================
// kf_fin: reduce slab partials -> softmax-weighted sum -> squash.
// mode 0: g_vcur = v1 + v2.  mode 1: write v3 to out.
// ============================================================================
__global__ void __launch_bounds__(32)
kf_fin(int mode, float* __restrict__ out) {
    const int bc = blockIdx.x;
    const int b  = bc >> 5;
    const int c  = bc & 31;
    const int t  = threadIdx.x;

    float acc = 0.f;
    if (t < 17) {
        for (int s = 0; s < NSPLIT; s++)
            acc += g_red[(((size_t)c * NSPLIT + s) * Bn + b) * 17 + t];
    }
    float D = __shfl_sync(0xffffffffu, acc, 16);
    float val = (t < OUTn) ? acc / D : 0.f;
    float sq = val * val;
    #pragma unroll
    for (int off = 16; off; off >>= 1) sq += __shfl_xor_sync(0xffffffffu, sq, off);
    float coef = (sq / (1.f + sq)) * rsqrtf(sq + 1e-8f);
    float v = val * coef;
    if (t < OUTn) {
        if (mode == 0)
            g_vcur[(size_t)bc * OUTn + t] = g_v1[(size_t)bc * OUTn + t] + v;
        else
            out[(size_t)bc * OUTn + t] = v;
    }
}

// ============================================================================
extern "C" void kernel_launch(void* const* d_in, const int* in_sizes, int n_in,
                              void* d_out, int out_size) {
    const float* x = (const float*)d_in[0];           // (64, 4608, 8)
    const float* w = (const float*)d_in[1];           // (4608, 32, 8, 16)
    float* out = (float*)d_out;                       // (64, 32, 16)

    k0_transpose<<<dim3(Rn * 2 / 32, Bn / 32), dim3(32, 8)>>>((const float4*)x);
    k1_uhat<<<dim3(Cn, NCHUNK), 256>>>(w);
    kf_v1<<<Bn * Cn, 32>>>();
    k2p<<<dim3(Cn, NSPLIT), 256>>>();
    kf_fin<<<Bn * Cn, 32>>>(0, out);
    k2p<<<dim3(Cn, NSPLIT), 256>>>();
    kf_fin<<<Bn * Cn, 32>>>(1, out);
}